// round 15
// baseline (speedup 1.0000x reference)
#include <cuda_runtime.h>
#include <math.h>

// ConvolutionalCapsule EM routing — fused, transposed weights, 4-warp CTAs
// @ occ 4, per-warp smem partials (R13 base). R15: 3-way i-interleave in the
// EM passes (three softmax chains in flight) + exp2-domain softmax (log2e
// folded into the per-pass constants; no FMUL in the exp chain).
// Shapes: pose [4,14,14,32,4,4], act [4,14,14,32], w [1,288,32,4,4],
//         beta_v/beta_a [1,1,1,32]; stride=1, routings=3.
// Output: pose [4,12,12,32,4,4] then activation [4,12,12,32]

#define EPSF 1e-9f

namespace {
constexpr int S   = 12;
constexpr int IC  = 32;
constexpr int O   = 32;
constexpr int I   = 288;   // 3*3*32
constexpr int PR  = 16;
constexpr int NW  = 4;     // warps per block; 72 i's per warp -> 24 triples
constexpr int NT  = 32 * NW;
constexpr int PAD = 17;    // conflict-free lane stride
constexpr int POSE_OUT = 4 * S * S * O * PR;
constexpr float L2E    = 1.4426950408889634f;  // log2(e)
constexpr float SHIFT2 = 63.4f;  // 44*log2e: zz2<=0 -> exp2 cannot overflow
}

// Transposed weights: g_wt[(i*4 + q)*32 + o] = { w[i,o,q,0..3] }
__device__ float4 g_wt[I * 4 * O];

__global__ void transpose_w_kernel(const float* __restrict__ w)
{
    int idx = blockIdx.x * blockDim.x + threadIdx.x;
    if (idx >= I * O * 4) return;
    const float4* w4 = reinterpret_cast<const float4*>(w);
    int q = idx & 3;
    int o = (idx >> 2) & 31;
    int i = idx >> 7;
    g_wt[(i * 4 + q) * 32 + o] = w4[idx];
}

// votes v[p*4+r] = sum_q pose[i,p,q] * w_t[i,q][o].r
__device__ __forceinline__ void compute_votes(const float4* __restrict__ pp,
                                              const float4* __restrict__ wt,
                                              float v[PR])
{
    float4 W0 = wt[0], W1 = wt[32], W2 = wt[64], W3 = wt[96];
    #pragma unroll
    for (int p = 0; p < 4; p++) {
        float4 P = pp[p];
        v[p*4+0] = fmaf(P.x, W0.x, fmaf(P.y, W1.x, fmaf(P.z, W2.x, P.w * W3.x)));
        v[p*4+1] = fmaf(P.x, W0.y, fmaf(P.y, W1.y, fmaf(P.z, W2.y, P.w * W3.y)));
        v[p*4+2] = fmaf(P.x, W0.z, fmaf(P.y, W1.z, fmaf(P.z, W2.z, P.w * W3.z)));
        v[p*4+3] = fmaf(P.x, W0.w, fmaf(P.y, W1.w, fmaf(P.z, W2.w, P.w * W3.w)));
    }
}

__global__ __launch_bounds__(NT, 4)
void capsule_em_kernel(const float* __restrict__ pose_in,
                       const float* __restrict__ act_in,
                       const float* __restrict__ beta_v,
                       const float* __restrict__ beta_a,
                       float* __restrict__ out)
{
    __shared__ float sh_pose[I * PR];
    __shared__ float sh_act[I];
    __shared__ float sP0[NW][O];          // per-warp partial S0
    __shared__ float sP1[NW][O * PAD];    // per-warp partial S1 (stride 17)
    __shared__ float sP2[NW][O * PAD];    // per-warp partial S2

    const int o   = threadIdx.x;       // lane = output capsule
    const int wy  = threadIdx.y;       // warp id (0..3)
    const int tid = wy * 32 + o;

    const int n   = blockIdx.x;
    const int b   = n / (S * S);
    const int rem = n % (S * S);
    const int oh  = rem / S;
    const int ow  = rem % S;

    // ---- load receptive field into SMEM ----
    {
        float4* dst4 = reinterpret_cast<float4*>(sh_pose);
        const float4* src4 = reinterpret_cast<const float4*>(pose_in);
        #pragma unroll 1
        for (int idx = tid; idx < I * 4; idx += NT) {
            int i  = idx >> 2, f = idx & 3;
            int k  = i >> 5,  ic = i & 31;
            int kh = k / 3,   kw = k % 3;
            long g = ((long)((b * 14 + oh + kh) * 14 + (ow + kw)) * IC + ic) * 4 + f;
            dst4[idx] = src4[g];
        }
        #pragma unroll 1
        for (int idx = tid; idx < I; idx += NT) {
            int k  = idx >> 5, ic = idx & 31;
            int kh = k / 3,    kw = k % 3;
            sh_act[idx] = act_in[((b * 14 + oh + kh) * 14 + (ow + kw)) * IC + ic];
        }
    }
    const float bv = beta_v[o];
    const float ba = beta_a[o];
    __syncthreads();

    // per-o expanded-quadratic constants in LOG2 domain:
    // q2 = sum_e v*(ivr*v + nB)   (ivr,nB pre-scaled by log2e)
    float ivr[PR], nB[PR];
    #pragma unroll
    for (int e = 0; e < PR; e++) { ivr[e] = 0.f; nB[e] = 0.f; }
    float Co2 = 0.f, act_o = 0.f;     // Co2 = (Co)*log2e - C2

    #pragma unroll 1
    for (int it = 0; it < 3; ++it) {
        float s0 = 0.f, s1[PR], s2[PR];
        #pragma unroll
        for (int e = 0; e < PR; e++) { s1[e] = 0.f; s2[e] = 0.f; }

        if (it == 0) {
            // uniform rr (1/32 folded into M-step): paired, no softmax chain
            #pragma unroll 1
            for (int ii = 0; ii < I / NW; ii += 2) {
                const int ia = wy + ii * NW;
                const int ib = ia + NW;
                float va[PR], vb[PR];
                compute_votes(reinterpret_cast<const float4*>(sh_pose) + (ia << 2),
                              g_wt + ia * 128 + o, va);
                compute_votes(reinterpret_cast<const float4*>(sh_pose) + (ib << 2),
                              g_wt + ib * 128 + o, vb);
                float rpa = sh_act[ia];
                float rpb = sh_act[ib];
                s0 += rpa + rpb;
                #pragma unroll
                for (int e = 0; e < PR; e++) {
                    float ta = rpa * va[e];
                    float tb = rpb * vb[e];
                    s1[e] += ta + tb;
                    s2[e] = fmaf(ta, va[e], fmaf(tb, vb[e], s2[e]));
                }
            }
        } else {
            // 3-way interleave: three softmax chains in flight per warp
            #pragma unroll 1
            for (int g = 0; g < I / (NW * 3); ++g) {
                const int i0 = wy + (g * 3) * NW;
                const int i1 = i0 + NW;
                const int i2 = i1 + NW;

                float v0[PR], v1[PR], v2[PR];
                compute_votes(reinterpret_cast<const float4*>(sh_pose) + (i0 << 2),
                              g_wt + i0 * 128 + o, v0);
                compute_votes(reinterpret_cast<const float4*>(sh_pose) + (i1 << 2),
                              g_wt + i1 * 128 + o, v1);
                compute_votes(reinterpret_cast<const float4*>(sh_pose) + (i2 << 2),
                              g_wt + i2 * 128 + o, v2);

                // q2 (expanded, log2 domain): 2 FMAs per element, 2-way trees
                float qa0 = 0.f, qa1 = 0.f;
                float qb0 = 0.f, qb1 = 0.f;
                float qc0 = 0.f, qc1 = 0.f;
                #pragma unroll
                for (int e = 0; e < PR; e += 2) {
                    float u;
                    u = fmaf(ivr[e+0], v0[e+0], nB[e+0]); qa0 = fmaf(v0[e+0], u, qa0);
                    u = fmaf(ivr[e+1], v0[e+1], nB[e+1]); qa1 = fmaf(v0[e+1], u, qa1);
                    u = fmaf(ivr[e+0], v1[e+0], nB[e+0]); qb0 = fmaf(v1[e+0], u, qb0);
                    u = fmaf(ivr[e+1], v1[e+1], nB[e+1]); qb1 = fmaf(v1[e+1], u, qb1);
                    u = fmaf(ivr[e+0], v2[e+0], nB[e+0]); qc0 = fmaf(v2[e+0], u, qc0);
                    u = fmaf(ivr[e+1], v2[e+1], nB[e+1]); qc1 = fmaf(v2[e+1], u, qc1);
                }
                // fixed-shift exp2 softmax over lanes (no max chain, no FMUL)
                float e0 = exp2f((Co2 + SHIFT2) - (qa0 + qa1));
                float e1 = exp2f((Co2 + SHIFT2) - (qb0 + qb1));
                float e2 = exp2f((Co2 + SHIFT2) - (qc0 + qc1));
                float sm0 = e0, sm1 = e1, sm2 = e2;
                #pragma unroll
                for (int off = 16; off; off >>= 1) {
                    sm0 += __shfl_xor_sync(0xffffffffu, sm0, off);
                    sm1 += __shfl_xor_sync(0xffffffffu, sm1, off);
                    sm2 += __shfl_xor_sync(0xffffffffu, sm2, off);
                }
                float rp0 = __fdividef(e0, sm0) * sh_act[i0];
                float rp1 = __fdividef(e1, sm1) * sh_act[i1];
                float rp2 = __fdividef(e2, sm2) * sh_act[i2];

                s0 += (rp0 + rp1) + rp2;
                #pragma unroll
                for (int e = 0; e < PR; e++) {
                    float t0 = rp0 * v0[e];
                    float t1 = rp1 * v1[e];
                    float t2 = rp2 * v2[e];
                    s1[e] += (t0 + t1) + t2;
                    s2[e] = fmaf(t0, v0[e], fmaf(t1, v1[e], fmaf(t2, v2[e], s2[e])));
                }
            }
        }

        // per-warp partials -> smem (conflict-free stride-17 STS)
        sP0[wy][o] = s0;
        #pragma unroll
        for (int e = 0; e < PR; e++) {
            sP1[wy][o * PAD + e] = s1[e];
            sP2[wy][o * PAD + e] = s2[e];
        }
        __syncthreads();

        // M-step (replicated across warps), 4-way reduction folded in.
        float S0raw = (sP0[0][o] + sP0[1][o]) + (sP0[2][o] + sP0[3][o]);
        float S0v   = (it == 0) ? S0raw * (1.0f / 32.0f) : S0raw;
        float invS0 = 1.0f / S0raw;
        float C2 = 0.f;
        float pv0 = 1.f, pv1 = 1.f, pv2 = 1.f, pv3 = 1.f;   // var products
        #pragma unroll
        for (int e = 0; e < PR; e++) {
            float S1e = (sP1[0][o * PAD + e] + sP1[1][o * PAD + e])
                      + (sP1[2][o * PAD + e] + sP1[3][o * PAD + e]);
            float S2e = (sP2[0][o * PAD + e] + sP2[1][o * PAD + e])
                      + (sP2[2][o * PAD + e] + sP2[3][o * PAD + e]);
            float m   = S1e * invS0;
            float var = fmaxf(S2e * invS0 - m * m, 1e-18f);
            float iv2 = (0.5f * L2E) / var;   // log2-domain inverse variance
            ivr[e] = iv2;
            nB[e]  = -2.0f * m * iv2;
            C2     = fmaf(iv2 * m, m, C2);
            if      (e < 4)  pv0 *= var;
            else if (e < 8)  pv1 *= var;
            else if (e < 12) pv2 *= var;
            else             pv3 *= var;
        }
        // sum log(sd+eps) ~= 0.5*log(prod var)  (natural log for the cost)
        float lsum = 0.5f * (__logf(pv0 * pv1) + __logf(pv2 * pv3));
        float cost     = (16.0f * bv + lsum) * S0v;
        float inv_temp = 1.0f + (float)it;   // 1, 2, 3
        act_o = 1.0f / (1.0f + __expf(-inv_temp * (ba - cost)));
        if (it < 2)
            Co2 = (__logf(act_o + EPSF) - lsum) * L2E - C2;
        __syncthreads();   // protect sP* from next pass's overwrites
    }

    // ---- write outputs (warp 0 only); means re-derived from partials ----
    if (wy == 0) {
        float S0raw = (sP0[0][o] + sP0[1][o]) + (sP0[2][o] + sP0[3][o]);
        float invS0 = 1.0f / S0raw;
        float4* op = reinterpret_cast<float4*>(out + ((long)n * O + o) * PR);
        #pragma unroll
        for (int p = 0; p < 4; p++) {
            float4 m4;
            float* r = &m4.x;
            #pragma unroll
            for (int c = 0; c < 4; c++) {
                int e = p * 4 + c;
                r[c] = ((sP1[0][o * PAD + e] + sP1[1][o * PAD + e])
                      + (sP1[2][o * PAD + e] + sP1[3][o * PAD + e])) * invS0;
            }
            op[p] = m4;
        }
        out[POSE_OUT + (long)n * O + o] = act_o;
    }
}

extern "C" void kernel_launch(void* const* d_in, const int* in_sizes, int n_in,
                              void* d_out, int out_size)
{
    const float* pose_in = (const float*)d_in[0];
    const float* act_in  = (const float*)d_in[1];
    const float* w       = (const float*)d_in[2];
    const float* beta_v  = (const float*)d_in[3];
    const float* beta_a  = (const float*)d_in[4];
    float* out = (float*)d_out;

    transpose_w_kernel<<<(I * O * 4 + 255) / 256, 256>>>(w);

    dim3 grid(4 * S * S);
    dim3 block(32, NW);
    capsule_em_kernel<<<grid, block>>>(pose_in, act_in, beta_v, beta_a, out);
}

// round 17
// speedup vs baseline: 1.0469x; 1.0469x over previous
#include <cuda_runtime.h>
#include <math.h>

// ConvolutionalCapsule EM routing — fused, transposed weights, paired i-steps,
// 4-warp CTAs @ occ 4, per-warp smem partials (R13 base), expanded
// Mahalanobis in LOG2 domain: q2 = sum v*(ivr*v+nB) with ivr,nB pre-scaled by
// log2e, so the softmax uses exp2f directly (no FMUL in the exp chain).
// Shapes: pose [4,14,14,32,4,4], act [4,14,14,32], w [1,288,32,4,4],
//         beta_v/beta_a [1,1,1,32]; stride=1, routings=3.
// Output: pose [4,12,12,32,4,4] then activation [4,12,12,32]

#define EPSF 1e-9f

namespace {
constexpr int S   = 12;
constexpr int IC  = 32;
constexpr int O   = 32;
constexpr int I   = 288;   // 3*3*32
constexpr int PR  = 16;
constexpr int NW  = 4;     // warps per block; 72 i's per warp -> 36 pairs
constexpr int NT  = 32 * NW;
constexpr int PAD = 17;    // conflict-free lane stride
constexpr int POSE_OUT = 4 * S * S * O * PR;
constexpr float L2E    = 1.4426950408889634f;  // log2(e)
constexpr float SHIFT2 = 63.4f;  // 44*log2e: zz2<=0 -> exp2 cannot overflow
}

// Transposed weights: g_wt[(i*4 + q)*32 + o] = { w[i,o,q,0..3] }
__device__ float4 g_wt[I * 4 * O];

__global__ void transpose_w_kernel(const float* __restrict__ w)
{
    int idx = blockIdx.x * blockDim.x + threadIdx.x;
    if (idx >= I * O * 4) return;
    const float4* w4 = reinterpret_cast<const float4*>(w);
    int q = idx & 3;
    int o = (idx >> 2) & 31;
    int i = idx >> 7;
    g_wt[(i * 4 + q) * 32 + o] = w4[idx];
}

// votes v[p*4+r] = sum_q pose[i,p,q] * w_t[i,q][o].r
__device__ __forceinline__ void compute_votes(const float4* __restrict__ pp,
                                              const float4* __restrict__ wt,
                                              float v[PR])
{
    float4 W0 = wt[0], W1 = wt[32], W2 = wt[64], W3 = wt[96];
    #pragma unroll
    for (int p = 0; p < 4; p++) {
        float4 P = pp[p];
        v[p*4+0] = fmaf(P.x, W0.x, fmaf(P.y, W1.x, fmaf(P.z, W2.x, P.w * W3.x)));
        v[p*4+1] = fmaf(P.x, W0.y, fmaf(P.y, W1.y, fmaf(P.z, W2.y, P.w * W3.y)));
        v[p*4+2] = fmaf(P.x, W0.z, fmaf(P.y, W1.z, fmaf(P.z, W2.z, P.w * W3.z)));
        v[p*4+3] = fmaf(P.x, W0.w, fmaf(P.y, W1.w, fmaf(P.z, W2.w, P.w * W3.w)));
    }
}

__global__ __launch_bounds__(NT, 4)
void capsule_em_kernel(const float* __restrict__ pose_in,
                       const float* __restrict__ act_in,
                       const float* __restrict__ beta_v,
                       const float* __restrict__ beta_a,
                       float* __restrict__ out)
{
    __shared__ float sh_pose[I * PR];
    __shared__ float sh_act[I];
    __shared__ float sP0[NW][O];          // per-warp partial S0
    __shared__ float sP1[NW][O * PAD];    // per-warp partial S1 (stride 17)
    __shared__ float sP2[NW][O * PAD];    // per-warp partial S2

    const int o   = threadIdx.x;       // lane = output capsule
    const int wy  = threadIdx.y;       // warp id (0..3)
    const int tid = wy * 32 + o;

    const int n   = blockIdx.x;
    const int b   = n / (S * S);
    const int rem = n % (S * S);
    const int oh  = rem / S;
    const int ow  = rem % S;

    // ---- load receptive field into SMEM ----
    {
        float4* dst4 = reinterpret_cast<float4*>(sh_pose);
        const float4* src4 = reinterpret_cast<const float4*>(pose_in);
        #pragma unroll 1
        for (int idx = tid; idx < I * 4; idx += NT) {
            int i  = idx >> 2, f = idx & 3;
            int k  = i >> 5,  ic = i & 31;
            int kh = k / 3,   kw = k % 3;
            long g = ((long)((b * 14 + oh + kh) * 14 + (ow + kw)) * IC + ic) * 4 + f;
            dst4[idx] = src4[g];
        }
        #pragma unroll 1
        for (int idx = tid; idx < I; idx += NT) {
            int k  = idx >> 5, ic = idx & 31;
            int kh = k / 3,    kw = k % 3;
            sh_act[idx] = act_in[((b * 14 + oh + kh) * 14 + (ow + kw)) * IC + ic];
        }
    }
    const float bv = beta_v[o];
    const float ba = beta_a[o];
    __syncthreads();

    // per-o expanded-quadratic constants in LOG2 domain
    float ivr[PR], nB[PR];
    #pragma unroll
    for (int e = 0; e < PR; e++) { ivr[e] = 0.f; nB[e] = 0.f; }
    float Co2 = 0.f, act_o = 0.f;     // log2-domain: Co*log2e - C2

    #pragma unroll 1
    for (int it = 0; it < 3; ++it) {
        float s0 = 0.f, s1[PR], s2[PR];
        #pragma unroll
        for (int e = 0; e < PR; e++) { s1[e] = 0.f; s2[e] = 0.f; }

        if (it == 0) {
            // uniform rr (1/32 folded into M-step): no softmax chain
            #pragma unroll 1
            for (int ii = 0; ii < I / NW; ii += 2) {
                const int ia = wy + ii * NW;
                const int ib = ia + NW;
                float va[PR], vb[PR];
                compute_votes(reinterpret_cast<const float4*>(sh_pose) + (ia << 2),
                              g_wt + ia * 128 + o, va);
                compute_votes(reinterpret_cast<const float4*>(sh_pose) + (ib << 2),
                              g_wt + ib * 128 + o, vb);
                float rpa = sh_act[ia];
                float rpb = sh_act[ib];
                s0 += rpa + rpb;
                #pragma unroll
                for (int e = 0; e < PR; e++) {
                    float ta = rpa * va[e];
                    float tb = rpb * vb[e];
                    s1[e] += ta + tb;
                    s2[e] = fmaf(ta, va[e], fmaf(tb, vb[e], s2[e]));
                }
            }
        } else {
            #pragma unroll 1
            for (int ii = 0; ii < I / NW; ii += 2) {
                const int ia = wy + ii * NW;
                const int ib = ia + NW;
                float aa = sh_act[ia];
                float ab = sh_act[ib];

                float va[PR], vb[PR];
                compute_votes(reinterpret_cast<const float4*>(sh_pose) + (ia << 2),
                              g_wt + ia * 128 + o, va);
                compute_votes(reinterpret_cast<const float4*>(sh_pose) + (ib << 2),
                              g_wt + ib * 128 + o, vb);

                // q2 (expanded, log2 domain): 2 FMAs per element, 4-way trees
                float qa0 = 0.f, qa1 = 0.f, qa2 = 0.f, qa3 = 0.f;
                float qb0 = 0.f, qb1 = 0.f, qb2 = 0.f, qb3 = 0.f;
                #pragma unroll
                for (int e = 0; e < PR; e += 4) {
                    float u;
                    u = fmaf(ivr[e+0], va[e+0], nB[e+0]); qa0 = fmaf(va[e+0], u, qa0);
                    u = fmaf(ivr[e+1], va[e+1], nB[e+1]); qa1 = fmaf(va[e+1], u, qa1);
                    u = fmaf(ivr[e+2], va[e+2], nB[e+2]); qa2 = fmaf(va[e+2], u, qa2);
                    u = fmaf(ivr[e+3], va[e+3], nB[e+3]); qa3 = fmaf(va[e+3], u, qa3);
                    u = fmaf(ivr[e+0], vb[e+0], nB[e+0]); qb0 = fmaf(vb[e+0], u, qb0);
                    u = fmaf(ivr[e+1], vb[e+1], nB[e+1]); qb1 = fmaf(vb[e+1], u, qb1);
                    u = fmaf(ivr[e+2], vb[e+2], nB[e+2]); qb2 = fmaf(vb[e+2], u, qb2);
                    u = fmaf(ivr[e+3], vb[e+3], nB[e+3]); qb3 = fmaf(vb[e+3], u, qb3);
                }
                // fixed-shift exp2 softmax over lanes (no max chain, no FMUL)
                float ea = exp2f((Co2 + SHIFT2) - ((qa0 + qa1) + (qa2 + qa3)));
                float eb = exp2f((Co2 + SHIFT2) - ((qb0 + qb1) + (qb2 + qb3)));
                float sma = ea, smb = eb;
                #pragma unroll
                for (int off = 16; off; off >>= 1) {
                    sma += __shfl_xor_sync(0xffffffffu, sma, off);
                    smb += __shfl_xor_sync(0xffffffffu, smb, off);
                }
                float rpa = __fdividef(ea, sma) * aa;
                float rpb = __fdividef(eb, smb) * ab;

                s0 += rpa + rpb;
                #pragma unroll
                for (int e = 0; e < PR; e++) {
                    float ta = rpa * va[e];
                    float tb = rpb * vb[e];
                    s1[e] += ta + tb;
                    s2[e] = fmaf(ta, va[e], fmaf(tb, vb[e], s2[e]));
                }
            }
        }

        // per-warp partials -> smem (conflict-free stride-17 STS)
        sP0[wy][o] = s0;
        #pragma unroll
        for (int e = 0; e < PR; e++) {
            sP1[wy][o * PAD + e] = s1[e];
            sP2[wy][o * PAD + e] = s2[e];
        }
        __syncthreads();

        // M-step (replicated across warps), 4-way reduction folded in.
        float S0raw = (sP0[0][o] + sP0[1][o]) + (sP0[2][o] + sP0[3][o]);
        float S0v   = (it == 0) ? S0raw * (1.0f / 32.0f) : S0raw;
        float invS0 = 1.0f / S0raw;
        float C2 = 0.f;
        float pv0 = 1.f, pv1 = 1.f, pv2 = 1.f, pv3 = 1.f;   // var products
        #pragma unroll
        for (int e = 0; e < PR; e++) {
            float S1e = (sP1[0][o * PAD + e] + sP1[1][o * PAD + e])
                      + (sP1[2][o * PAD + e] + sP1[3][o * PAD + e]);
            float S2e = (sP2[0][o * PAD + e] + sP2[1][o * PAD + e])
                      + (sP2[2][o * PAD + e] + sP2[3][o * PAD + e]);
            float m   = S1e * invS0;
            float var = fmaxf(S2e * invS0 - m * m, 1e-18f);
            float iv2 = (0.5f * L2E) / var;   // log2-domain inverse variance
            ivr[e] = iv2;
            nB[e]  = -2.0f * m * iv2;
            C2     = fmaf(iv2 * m, m, C2);
            if      (e < 4)  pv0 *= var;
            else if (e < 8)  pv1 *= var;
            else if (e < 12) pv2 *= var;
            else             pv3 *= var;
        }
        // sum log(sd+eps) ~= 0.5*log(prod var)  (natural log for the cost)
        float lsum = 0.5f * (__logf(pv0 * pv1) + __logf(pv2 * pv3));
        float cost     = (16.0f * bv + lsum) * S0v;
        float inv_temp = 1.0f + (float)it;   // 1, 2, 3
        act_o = 1.0f / (1.0f + __expf(-inv_temp * (ba - cost)));
        if (it < 2)
            Co2 = (__logf(act_o + EPSF) - lsum) * L2E - C2;
        __syncthreads();   // protect sP* from next pass's overwrites
    }

    // ---- write outputs (warp 0 only); means re-derived from partials ----
    if (wy == 0) {
        float S0raw = (sP0[0][o] + sP0[1][o]) + (sP0[2][o] + sP0[3][o]);
        float invS0 = 1.0f / S0raw;
        float4* op = reinterpret_cast<float4*>(out + ((long)n * O + o) * PR);
        #pragma unroll
        for (int p = 0; p < 4; p++) {
            float4 m4;
            float* r = &m4.x;
            #pragma unroll
            for (int c = 0; c < 4; c++) {
                int e = p * 4 + c;
                r[c] = ((sP1[0][o * PAD + e] + sP1[1][o * PAD + e])
                      + (sP1[2][o * PAD + e] + sP1[3][o * PAD + e])) * invS0;
            }
            op[p] = m4;
        }
        out[POSE_OUT + (long)n * O + o] = act_o;
    }
}

extern "C" void kernel_launch(void* const* d_in, const int* in_sizes, int n_in,
                              void* d_out, int out_size)
{
    const float* pose_in = (const float*)d_in[0];
    const float* act_in  = (const float*)d_in[1];
    const float* w       = (const float*)d_in[2];
    const float* beta_v  = (const float*)d_in[3];
    const float* beta_a  = (const float*)d_in[4];
    float* out = (float*)d_out;

    transpose_w_kernel<<<(I * O * 4 + 255) / 256, 256>>>(w);

    dim3 grid(4 * S * S);
    dim3 block(32, NW);
    capsule_em_kernel<<<grid, block>>>(pose_in, act_in, beta_v, beta_a, out);
}